// round 16
// baseline (speedup 1.0000x reference)
#include <cuda_runtime.h>
#include <cfloat>
#include <math.h>
#include <stdint.h>

// Problem constants (fixed shapes from reference)
#define BB 4
#define NN 4096
#define KK 20
#define QPB 16                // kNN queries per block (1 per warp, 512 threads)
#define PP (BB * NN * KK)     // 327680 positions
#define BN_TOT (BB * NN)      // 16384 (b,n) groups
#define NB1 (PP / 256)        // stats1 blocks = 1280
#define NBG (PP / 128)        // gemm blocks   = 2560

// ---------------------------------------------------------------------------
// Scratch in __device__ globals (no allocation allowed in kernel_launch)
// ---------------------------------------------------------------------------
__device__ float    g_y2[128 * PP];
__device__ int      g_idx[BB * NN * KK];
__device__ unsigned g_mx[128 * BN_TOT];   // okey-encoded per-(o,bn) max
__device__ unsigned g_mn[128 * BN_TOT];   // okey-encoded per-(o,bn) min
__device__ float    g_ps[128 * NBG];      // BN partials (reused for f-moments)
__device__ float    g_pq[128 * NBG];
__device__ float    g_sc1[64],  g_sh1[64];
__device__ float    g_sc2[128], g_sh2[128];
__device__ float    g_sc3[128], g_sh3[128];

// ---------------------------------------------------------------------------
// Packed fp32x2 helpers (FFMA2)
// ---------------------------------------------------------------------------
__device__ __forceinline__ unsigned long long splat2(float v) {
    unsigned long long r;
    asm("mov.b64 %0, {%1, %1};" : "=l"(r) : "f"(v));
    return r;
}
__device__ __forceinline__ void ffma2(unsigned long long& d,
                                      unsigned long long a,
                                      unsigned long long b) {
    asm("fma.rn.f32x2 %0, %1, %2, %0;" : "+l"(d) : "l"(a), "l"(b));
}
__device__ __forceinline__ float2 unpack2(unsigned long long v) {
    float2 f;
    asm("mov.b64 {%0, %1}, %2;" : "=f"(f.x), "=f"(f.y) : "l"(v));
    return f;
}

// Orderable uint key: ascending float order -> ascending unsigned order.
__device__ __forceinline__ unsigned okey(float f) {
    unsigned u = __float_as_uint(f);
    return u ^ (((unsigned)((int)u >> 31)) | 0x80000000u);
}
__device__ __forceinline__ float okey_inv(unsigned k) {
    unsigned u = (k & 0x80000000u) ? (k ^ 0x80000000u) : ~k;
    return __uint_as_float(u);
}

// ---------------------------------------------------------------------------
// K0: warp-cooperative exact kNN (k=20), REDUX inserts — R9-proven (92.8us).
// ---------------------------------------------------------------------------
__global__ void __launch_bounds__(512) knn_warp_kernel(
    const float* __restrict__ x, int* __restrict__ idxo)
{
    extern __shared__ float4 pts[];
    const int b = blockIdx.y;
    const float* xb = x + (size_t)b * NN * 3;
    const int tid = threadIdx.x, lane = tid & 31, w = tid >> 5;

    for (int t = tid; t < NN; t += 512) {
        float px = xb[t * 3 + 0], py = xb[t * 3 + 1], pz = xb[t * 3 + 2];
        pts[t] = make_float4(px, py, pz, px * px + py * py + pz * pz);
    }
    __syncthreads();

    const int i = blockIdx.x * QPB + w;
    float4 q = pts[i];
    const float qx = 2.f * q.x, qy = 2.f * q.y, qz = 2.f * q.z;

    unsigned my_k = (lane < KK) ? okey(-FLT_MAX) : okey(FLT_MAX);
    int      my_j = 0x7fff0000 | lane;
    unsigned wkey = okey(-FLT_MAX);

    for (int jc = 0; jc < NN; jc += 32) {
        float4 p = pts[jc + lane];
        float s = fmaf(qx, p.x, fmaf(qy, p.y, fmaf(qz, p.z, -p.w)));
        unsigned k = okey(s);
        unsigned mask = __ballot_sync(0xffffffffu, k > wkey);
        while (mask) {
            const int l = __ffs(mask) - 1;
            mask &= mask - 1;
            const unsigned kc = __shfl_sync(0xffffffffu, k, l);
            if (kc > wkey) {
                const unsigned umin = __reduce_min_sync(0xffffffffu, my_k);
                const bool tied = (my_k == umin);
                const int jmax = __reduce_max_sync(0xffffffffu, tied ? my_j : -1);
                if (tied && my_j == jmax) { my_k = kc; my_j = jc + l; }
                wkey = __reduce_min_sync(0xffffffffu, my_k);
            }
        }
    }

    if (lane < KK)
        idxo[((size_t)b * NN + i) * KK + lane] = my_j;
}

// ---------------------------------------------------------------------------
// stats1: accumulate f-moments over all P positions (proven).
// ---------------------------------------------------------------------------
__global__ void __launch_bounds__(256) stats1_kernel(
    const float* __restrict__ x, const int* __restrict__ idx,
    float* __restrict__ pf)
{
    const int tid  = threadIdx.x;
    const int lane = tid & 31;
    const int warp = tid >> 5;
    const int p  = blockIdx.x * 256 + tid;
    const int bn = p / KK;
    const int b  = bn >> 12;
    const int j  = idx[p];

    const float* xi = x + (size_t)bn * 3;
    const float* xj = x + ((size_t)b * NN + j) * 3;
    float f[6];
    f[3] = xi[0]; f[4] = xi[1]; f[5] = xi[2];
    f[0] = xj[0] - f[3]; f[1] = xj[1] - f[4]; f[2] = xj[2] - f[5];

    float acc[27];
#pragma unroll
    for (int d = 0; d < 6; d++) acc[d] = f[d];
    {
        int k = 6;
#pragma unroll
        for (int d = 0; d < 6; d++)
#pragma unroll
            for (int e = d; e < 6; e++) acc[k++] = f[d] * f[e];
    }

    __shared__ float s_m[27 * 8];
#pragma unroll
    for (int s = 0; s < 27; s++) {
        float v = acc[s];
#pragma unroll
        for (int m = 16; m > 0; m >>= 1)
            v += __shfl_xor_sync(0xffffffffu, v, m);
        if (lane == 0) s_m[s * 8 + warp] = v;
    }
    __syncthreads();

    if (tid < 27) {
        float a = 0.f;
#pragma unroll
        for (int w = 0; w < 8; w++) a += s_m[tid * 8 + w];
        pf[tid * NB1 + blockIdx.x] = a;
    }
}

// ---------------------------------------------------------------------------
// affine1: warp-parallel moment reduction -> analytic BN1 affine (proven).
// ---------------------------------------------------------------------------
__global__ void affine1_kernel(const float* __restrict__ pf,
                               const float* __restrict__ W1,
                               const float* __restrict__ b1,
                               const float* __restrict__ g1,
                               const float* __restrict__ be1,
                               float* __restrict__ sc,
                               float* __restrict__ sh)
{
    __shared__ double st[32];
    const int lane = threadIdx.x & 31;
    const int warp = threadIdx.x >> 5;

#pragma unroll
    for (int g = 0; g < 4; ++g) {
        const int s = warp + g * 8;
        if (s < 27) {
            double a = 0.0;
            for (int i = lane; i < NB1; i += 32)
                a += (double)pf[s * NB1 + i];
#pragma unroll
            for (int m = 16; m > 0; m >>= 1)
                a += __shfl_xor_sync(0xffffffffu, a, m);
            if (lane == 0) st[s] = a;
        }
    }
    __syncthreads();

    if (threadIdx.x < 64) {
        const int c = threadIdx.x;
        double w[6];
#pragma unroll
        for (int d = 0; d < 6; d++) w[d] = (double)W1[c * 6 + d];
        const double b = (double)b1[c];
        double ws = 0.0;
#pragma unroll
        for (int d = 0; d < 6; d++) ws += w[d] * st[d];
        double wmw = 0.0;
        int k = 6;
#pragma unroll
        for (int d = 0; d < 6; d++)
#pragma unroll
            for (int e = d; e < 6; e++, k++)
                wmw += ((d == e) ? w[d] * w[d] : 2.0 * w[d] * w[e]) * st[k];
        const double Pd = (double)PP;
        double mean = ws / Pd + b;
        double e2   = (wmw + 2.0 * b * ws) / Pd + b * b;
        double var  = e2 - mean * mean;
        double inv  = (double)g1[c] / sqrt(var + 1e-5);
        sc[c] = (float)inv;
        sh[c] = (float)((double)be1[c] - mean * inv);
    }
}

// ---------------------------------------------------------------------------
// Reduce per-block partials -> fused BN affine (proven).
// ---------------------------------------------------------------------------
__global__ void reduce_kernel(const float* __restrict__ ps,
                              const float* __restrict__ pq, int nb,
                              const float* __restrict__ gamma,
                              const float* __restrict__ beta,
                              float* __restrict__ scale,
                              float* __restrict__ shift)
{
    const int c = blockIdx.x;
    double s = 0.0, q = 0.0;
    for (int i = threadIdx.x; i < nb; i += 256) {
        s += (double)ps[c * nb + i];
        q += (double)pq[c * nb + i];
    }
    __shared__ double r1[256], r2[256];
    r1[threadIdx.x] = s; r2[threadIdx.x] = q;
    __syncthreads();
    for (int off = 128; off > 0; off >>= 1) {
        if (threadIdx.x < off) {
            r1[threadIdx.x] += r1[threadIdx.x + off];
            r2[threadIdx.x] += r2[threadIdx.x + off];
        }
        __syncthreads();
    }
    if (threadIdx.x == 0) {
        double mean = r1[0] / (double)PP;
        double var  = r2[0] / (double)PP - mean * mean;
        double inv  = (double)gamma[c] / sqrt(var + 1e-5);
        scale[c] = (float)inv;
        shift[c] = (float)((double)beta[c] - mean * inv);
    }
}

// ---------------------------------------------------------------------------
// init: seed okey max/min arrays (atomicMax/Min identities).
// ---------------------------------------------------------------------------
__global__ void initmm_kernel(unsigned* __restrict__ mx, unsigned* __restrict__ mn)
{
    const int stride = gridDim.x * blockDim.x;
    for (int t = blockIdx.x * blockDim.x + threadIdx.x;
         t < 128 * BN_TOT; t += stride) {
        mx[t] = 0u;
        mn[t] = 0xFFFFFFFFu;
    }
}

// ---------------------------------------------------------------------------
// Fused conv1+BN1+relu+conv2 GEMM (measured 153.6us — unchanged).
// ---------------------------------------------------------------------------
__global__ void __launch_bounds__(256, 2) gemm_fused_kernel(
    const float* __restrict__ x,
    const int* __restrict__ idx,
    const float* __restrict__ W1,
    const float* __restrict__ b1,
    const float* __restrict__ sc1,
    const float* __restrict__ sh1,
    const float* __restrict__ W,     // W2 [128][64]
    const float* __restrict__ bias,  // b2
    float* __restrict__ yout,
    float* __restrict__ ps,
    float* __restrict__ pq)
{
    extern __shared__ float sh[];
    float* Wsh   = sh;                     // [64][132] transposed W2
    float* Ash   = Wsh + 64 * 132;         // [64][128]
    float* fs    = Ash + 64 * 128;         // [128][7]
    float* W1sh  = fs + 128 * 7;           // [64][6]
    float* b1sh  = W1sh + 64 * 6;          // [64]
    float* sc1sh = b1sh + 64;              // [64]
    float* sh1sh = sc1sh + 64;             // [64]
    const int tid = threadIdx.x;

    for (int t = tid; t < 128 * 64; t += 256) {
        int o = t >> 6, c = t & 63;
        Wsh[c * 132 + o] = W[t];
    }
    for (int t = tid; t < 64 * 6; t += 256) W1sh[t] = W1[t];
    if (tid < 64) {
        b1sh[tid]  = b1[tid];
        sc1sh[tid] = sc1[tid];
        sh1sh[tid] = sh1[tid];
    }

    const int pbase = blockIdx.x * 128;
    if (tid < 128) {
        const int p  = pbase + tid;
        const int bn = p / KK;
        const int b  = bn >> 12;
        const int j  = idx[p];
        const float* xi = x + (size_t)bn * 3;
        const float* xj = x + ((size_t)b * NN + j) * 3;
        float xi0 = xi[0], xi1 = xi[1], xi2 = xi[2];
        fs[tid * 7 + 0] = xj[0] - xi0;
        fs[tid * 7 + 1] = xj[1] - xi1;
        fs[tid * 7 + 2] = xj[2] - xi2;
        fs[tid * 7 + 3] = xi0;
        fs[tid * 7 + 4] = xi1;
        fs[tid * 7 + 5] = xi2;
    }
    __syncthreads();

    for (int t = tid; t < 64 * 128; t += 256) {
        int c = t >> 7, p = t & 127;
        const float* w = W1sh + c * 6;
        const float* f = fs + p * 7;
        float a = b1sh[c];
        a = fmaf(w[0], f[0], a);
        a = fmaf(w[1], f[1], a);
        a = fmaf(w[2], f[2], a);
        a = fmaf(w[3], f[3], a);
        a = fmaf(w[4], f[4], a);
        a = fmaf(w[5], f[5], a);
        Ash[t] = fmaxf(fmaf(a, sc1sh[c], sh1sh[c]), 0.f);
    }
    __syncthreads();

    const int tx = tid & 15;
    const int ty = tid >> 4;

    unsigned long long acc[8][4];
#pragma unroll
    for (int i = 0; i < 8; i++)
#pragma unroll
        for (int jp = 0; jp < 4; jp++) acc[i][jp] = 0ULL;

#pragma unroll 4
    for (int c = 0; c < 64; ++c) {
        ulonglong2 A0 = *(const ulonglong2*)(Ash + c * 128 + tx * 4);
        ulonglong2 A1 = *(const ulonglong2*)(Ash + c * 128 + 64 + tx * 4);
        unsigned long long av[4] = {A0.x, A0.y, A1.x, A1.y};
        float4 w0 = *(const float4*)(Wsh + c * 132 + ty * 4);
        float4 w1 = *(const float4*)(Wsh + c * 132 + 64 + ty * 4);
        float wf[8] = {w0.x, w0.y, w0.z, w0.w, w1.x, w1.y, w1.z, w1.w};
#pragma unroll
        for (int i = 0; i < 8; i++) {
            unsigned long long wsp = splat2(wf[i]);
#pragma unroll
            for (int jp = 0; jp < 4; jp++) ffma2(acc[i][jp], wsp, av[jp]);
        }
    }

#pragma unroll
    for (int i = 0; i < 8; i++) {
        const int o = (i < 4) ? (ty * 4 + i) : (64 + ty * 4 + (i - 4));
        const float bo = bias[o];
        float2 p0 = unpack2(acc[i][0]);
        float2 p1 = unpack2(acc[i][1]);
        float2 p2 = unpack2(acc[i][2]);
        float2 p3 = unpack2(acc[i][3]);
        float v0 = p0.x + bo, v1 = p0.y + bo, v2 = p1.x + bo, v3 = p1.y + bo;
        float v4 = p2.x + bo, v5 = p2.y + bo, v6 = p3.x + bo, v7 = p3.y + bo;
        float* dst = yout + (size_t)o * PP + pbase;
        *(float4*)(dst + tx * 4)      = make_float4(v0, v1, v2, v3);
        *(float4*)(dst + 64 + tx * 4) = make_float4(v4, v5, v6, v7);

        float s = v0 + v1 + v2 + v3 + v4 + v5 + v6 + v7;
        float q = v0 * v0 + v1 * v1 + v2 * v2 + v3 * v3
                + v4 * v4 + v5 * v5 + v6 * v6 + v7 * v7;
#pragma unroll
        for (int m = 8; m > 0; m >>= 1) {
            s += __shfl_xor_sync(0xffffffffu, s, m, 16);
            q += __shfl_xor_sync(0xffffffffu, q, m, 16);
        }
        if (tx == 0) {
            ps[(size_t)o * NBG + blockIdx.x] = s;
            pq[(size_t)o * NBG + blockIdx.x] = q;
        }
    }
}

// ---------------------------------------------------------------------------
// GEMM layer3 (CIN=128): proven FFMA2 mainloop; fused max/min epilogue.
// FIX vs last round: a 128-tile can overlap up to EIGHT k-groups
// (pbase%20 >= 13) — loop gi over 8, guarded.
// ---------------------------------------------------------------------------
__global__ void __launch_bounds__(256, 2) gemm3_kernel(
    const float* __restrict__ yin,
    const float* __restrict__ W,
    const float* __restrict__ bias,
    const float* __restrict__ scale,
    const float* __restrict__ shift,
    unsigned* __restrict__ gmx,
    unsigned* __restrict__ gmn,
    float* __restrict__ ps,
    float* __restrict__ pq)
{
    extern __shared__ float sh[];
    float* Wsh = sh;                  // transposed [128][132]
    float* Ash = sh + 132 * 128;      // [64][128] k-chunk (reused in epilogue)
    const int tid = threadIdx.x;

    for (int t = tid; t < 128 * 128; t += 256) {
        int o = t >> 7, c = t & 127;
        Wsh[c * 132 + o] = W[t];
    }

    const int pbase = blockIdx.x * 128;
    const int tx = tid & 15;
    const int ty = tid >> 4;

    unsigned long long acc[8][4];
#pragma unroll
    for (int i = 0; i < 8; i++)
#pragma unroll
        for (int jp = 0; jp < 4; jp++) acc[i][jp] = 0ULL;

#pragma unroll
    for (int kc = 0; kc < 2; ++kc) {
        __syncthreads();
        for (int t = tid; t < 64 * 128; t += 256) {
            int c = t >> 7, p = t & 127;
            int cg = kc * 64 + c;
            float v = yin[(size_t)cg * PP + pbase + p];
            v = fmaf(v, scale[cg], shift[cg]);
            Ash[t] = fmaxf(v, 0.f);
        }
        __syncthreads();

#pragma unroll 4
        for (int c = 0; c < 64; ++c) {
            const int cg = kc * 64 + c;
            ulonglong2 A0 = *(const ulonglong2*)(Ash + c * 128 + tx * 4);
            ulonglong2 A1 = *(const ulonglong2*)(Ash + c * 128 + 64 + tx * 4);
            unsigned long long av[4] = {A0.x, A0.y, A1.x, A1.y};
            float4 w0 = *(const float4*)(Wsh + cg * 132 + ty * 4);
            float4 w1 = *(const float4*)(Wsh + cg * 132 + 64 + ty * 4);
            float wf[8] = {w0.x, w0.y, w0.z, w0.w, w1.x, w1.y, w1.z, w1.w};
#pragma unroll
            for (int i = 0; i < 8; i++) {
                unsigned long long wsp = splat2(wf[i]);
#pragma unroll
                for (int jp = 0; jp < 4; jp++) ffma2(acc[i][jp], wsp, av[jp]);
            }
        }
    }

    // Epilogue: reuse Ash (32KB) as run max/min buffers [128 o][32 runs].
    __syncthreads();                 // all mainloop Ash reads complete
    float* rmx = Ash;                // 128*32 = 4096 floats
    float* rmn = Ash + 4096;         // 4096 floats

#pragma unroll
    for (int i = 0; i < 8; i++) {
        const int o = (i < 4) ? (ty * 4 + i) : (64 + ty * 4 + (i - 4));
        const float bo = bias[o];
        float2 p0 = unpack2(acc[i][0]);
        float2 p1 = unpack2(acc[i][1]);
        float2 p2 = unpack2(acc[i][2]);
        float2 p3 = unpack2(acc[i][3]);
        float v0 = p0.x + bo, v1 = p0.y + bo, v2 = p1.x + bo, v3 = p1.y + bo;
        float v4 = p2.x + bo, v5 = p2.y + bo, v6 = p3.x + bo, v7 = p3.y + bo;

        // BN3 partial sums (deterministic, unchanged)
        float s = v0 + v1 + v2 + v3 + v4 + v5 + v6 + v7;
        float q = v0 * v0 + v1 * v1 + v2 * v2 + v3 * v3
                + v4 * v4 + v5 * v5 + v6 * v6 + v7 * v7;
#pragma unroll
        for (int m = 8; m > 0; m >>= 1) {
            s += __shfl_xor_sync(0xffffffffu, s, m, 16);
            q += __shfl_xor_sync(0xffffffffu, q, m, 16);
        }
        if (tx == 0) {
            ps[(size_t)o * NBG + blockIdx.x] = s;
            pq[(size_t)o * NBG + blockIdx.x] = q;
        }

        // 4-position run max/min (runs are k-group aligned since 4 | 20)
        rmx[o * 32 + tx]      = fmaxf(fmaxf(v0, v1), fmaxf(v2, v3));
        rmn[o * 32 + tx]      = fminf(fminf(v0, v1), fminf(v2, v3));
        rmx[o * 32 + 16 + tx] = fmaxf(fmaxf(v4, v5), fmaxf(v6, v7));
        rmn[o * 32 + 16 + tx] = fminf(fminf(v4, v5), fminf(v6, v7));
    }
    __syncthreads();

    // Per-(o, k-group) reduction over runs + deterministic okey atomics.
    // A tile overlaps up to 8 groups (gi in [0,8)); guard skips phantoms.
    const int run0 = pbase >> 2;     // global run index of local run 0
    const int G0   = pbase / KK;     // first k-group overlapping tile
    for (int pr = tid; pr < 128 * 8; pr += 256) {
        const int o  = pr & 127;
        const int gi = pr >> 7;
        const int G  = G0 + gi;
        if (G * KK >= pbase + 128) continue;   // group beyond tile
        int rlo = 5 * G - run0;     if (rlo < 0)  rlo = 0;
        int rhi = 5 * G + 4 - run0; if (rhi > 31) rhi = 31;
        float mx = -FLT_MAX, mn = FLT_MAX;
        for (int r = rlo; r <= rhi; ++r) {
            mx = fmaxf(mx, rmx[o * 32 + r]);
            mn = fminf(mn, rmn[o * 32 + r]);
        }
        atomicMax(gmx + (size_t)o * BN_TOT + G, okey(mx));
        atomicMin(gmn + (size_t)o * BN_TOT + G, okey(mn));
    }
}

// ---------------------------------------------------------------------------
// finalize: out[b][o][n] = BN3 affine of (scale>=0 ? max : min).
// ---------------------------------------------------------------------------
__global__ void finalize_kernel(const unsigned* __restrict__ gmx,
                                const unsigned* __restrict__ gmn,
                                const float* __restrict__ scale,
                                const float* __restrict__ shift,
                                float* __restrict__ out)
{
    const int t  = blockIdx.x * 256 + threadIdx.x;   // 0..128*BN_TOT-1
    const int o  = t >> 14;
    const int bn = t & (BN_TOT - 1);
    const int b  = bn >> 12;
    const int n  = bn & (NN - 1);
    const float sc = scale[o], sf = shift[o];
    const unsigned k = (sc >= 0.f) ? gmx[t] : gmn[t];
    out[((size_t)b * 128 + o) * NN + n] = fmaf(sc, okey_inv(k), sf);
}

// ---------------------------------------------------------------------------
// Launcher: graph-capturable, allocation-free.
// ---------------------------------------------------------------------------
extern "C" void kernel_launch(void* const* d_in, const int* in_sizes, int n_in,
                              void* d_out, int out_size)
{
    const float* x   = (const float*)d_in[0];
    const float* W1  = (const float*)d_in[1];
    const float* b1  = (const float*)d_in[2];
    const float* g1  = (const float*)d_in[3];
    const float* be1 = (const float*)d_in[4];
    const float* W2  = (const float*)d_in[5];
    const float* b2  = (const float*)d_in[6];
    const float* g2  = (const float*)d_in[7];
    const float* be2 = (const float*)d_in[8];
    const float* W3  = (const float*)d_in[9];
    const float* b3  = (const float*)d_in[10];
    const float* g3  = (const float*)d_in[11];
    const float* be3 = (const float*)d_in[12];
    float* out = (float*)d_out;

    void *y2p, *idxp, *mxp, *mnp, *psp, *pqp;
    void *sc1p, *sh1p, *sc2p, *sh2p, *sc3p, *sh3p;
    cudaGetSymbolAddress(&y2p,  g_y2);
    cudaGetSymbolAddress(&idxp, g_idx);
    cudaGetSymbolAddress(&mxp,  g_mx);
    cudaGetSymbolAddress(&mnp,  g_mn);
    cudaGetSymbolAddress(&psp,  g_ps);
    cudaGetSymbolAddress(&pqp,  g_pq);
    cudaGetSymbolAddress(&sc1p, g_sc1);  cudaGetSymbolAddress(&sh1p, g_sh1);
    cudaGetSymbolAddress(&sc2p, g_sc2);  cudaGetSymbolAddress(&sh2p, g_sh2);
    cudaGetSymbolAddress(&sc3p, g_sc3);  cudaGetSymbolAddress(&sh3p, g_sh3);

    const int smemF = (64 * 132 + 64 * 128 + 128 * 7 + 64 * 6 + 3 * 64) * 4; // 72448
    const int smem3 = (132 * 128 + 64 * 128) * 4;                             // 100352
    cudaFuncSetAttribute(knn_warp_kernel,  cudaFuncAttributeMaxDynamicSharedMemorySize, 65536);
    cudaFuncSetAttribute(gemm_fused_kernel,cudaFuncAttributeMaxDynamicSharedMemorySize, smemF);
    cudaFuncSetAttribute(gemm3_kernel,     cudaFuncAttributeMaxDynamicSharedMemorySize, smem3);

    // K0: warp-cooperative kNN (proven)
    knn_warp_kernel<<<dim3(NN / QPB, BB), 512, 65536>>>(x, (int*)idxp);

    // BN1 via f-moments (analytic; y1 never materialized)
    stats1_kernel<<<NB1, 256>>>(x, (const int*)idxp, (float*)psp);
    affine1_kernel<<<1, 256>>>((const float*)psp, W1, b1, g1, be1,
                               (float*)sc1p, (float*)sh1p);

    // conv1+BN1+relu+conv2 fused + BN2 partials   (launch #4 -> ncu window)
    gemm_fused_kernel<<<NBG, 256, smemF>>>(x, (const int*)idxp, W1, b1,
                                           (const float*)sc1p, (const float*)sh1p,
                                           W2, b2, (float*)y2p,
                                           (float*)psp, (float*)pqp);

    // seed max/min key arrays (independent; before gemm3)
    initmm_kernel<<<2048, 256>>>((unsigned*)mxp, (unsigned*)mnp);

    reduce_kernel<<<128, 256>>>((const float*)psp, (const float*)pqp, NBG,
                                g2, be2, (float*)sc2p, (float*)sh2p);

    // conv3 + fused per-group max/min + BN3 partials (y3 never materialized)
    gemm3_kernel<<<NBG, 256, smem3>>>((const float*)y2p, W3, b3,
                                      (const float*)sc2p, (const float*)sh2p,
                                      (unsigned*)mxp, (unsigned*)mnp,
                                      (float*)psp, (float*)pqp);
    reduce_kernel<<<128, 256>>>((const float*)psp, (const float*)pqp, NBG,
                                g3, be3, (float*)sc3p, (float*)sh3p);

    // BN3 affine + select max/min
    finalize_kernel<<<(128 * BN_TOT) / 256, 256>>>((const unsigned*)mxp,
                                                   (const unsigned*)mnp,
                                                   (const float*)sc3p,
                                                   (const float*)sh3p,
                                                   out);
}

// round 17
// speedup vs baseline: 1.0774x; 1.0774x over previous
#include <cuda_runtime.h>
#include <cfloat>
#include <math.h>
#include <stdint.h>

// Problem constants (fixed shapes from reference)
#define BB 4
#define NN 4096
#define KK 20
#define QPB 16                // kNN queries per block (1 per warp, 512 threads)
#define PP (BB * NN * KK)     // 327680 positions
#define NBK ((NN / QPB) * BB) // knn blocks = 1024 (also stats partial count)
#define NBG (PP / 128)        // gemm blocks = 2560

// ---------------------------------------------------------------------------
// Scratch in __device__ globals (no allocation allowed in kernel_launch)
// ---------------------------------------------------------------------------
__device__ float g_y2[128 * PP];
__device__ float g_y3[128 * PP];
__device__ int   g_idx[BB * NN * KK];
__device__ float g_pf[27 * NBK];      // f-moment block partials
__device__ float g_ps[128 * NBG];     // BN partials
__device__ float g_pq[128 * NBG];
__device__ float g_sc1[64],  g_sh1[64];
__device__ float g_sc2[128], g_sh2[128];
__device__ float g_sc3[128], g_sh3[128];

// ---------------------------------------------------------------------------
// Packed fp32x2 helpers (FFMA2)
// ---------------------------------------------------------------------------
__device__ __forceinline__ unsigned long long splat2(float v) {
    unsigned long long r;
    asm("mov.b64 %0, {%1, %1};" : "=l"(r) : "f"(v));
    return r;
}
__device__ __forceinline__ void ffma2(unsigned long long& d,
                                      unsigned long long a,
                                      unsigned long long b) {
    asm("fma.rn.f32x2 %0, %1, %2, %0;" : "+l"(d) : "l"(a), "l"(b));
}
__device__ __forceinline__ float2 unpack2(unsigned long long v) {
    float2 f;
    asm("mov.b64 {%0, %1}, %2;" : "=f"(f.x), "=f"(f.y) : "l"(v));
    return f;
}

// Orderable uint key: ascending float order -> ascending unsigned order.
__device__ __forceinline__ unsigned okey(float f) {
    unsigned u = __float_as_uint(f);
    return u ^ (((unsigned)((int)u >> 31)) | 0x80000000u);
}

// ---------------------------------------------------------------------------
// K0: warp-cooperative exact kNN (k=20), REDUX inserts (R9-proven mainloop)
// + NEW epilogue: per-query f-moment accumulation (replaces stats1 kernel).
// f = (xj-xi, xi); stats: S[0..5], M upper-tri (21) = 27 values.
// Deterministic: fixed shfl tree per warp + fixed smem tree per block.
// ---------------------------------------------------------------------------
__global__ void __launch_bounds__(512) knn_warp_kernel(
    const float* __restrict__ x, int* __restrict__ idxo,
    float* __restrict__ pf)
{
    extern __shared__ float4 pts[];
    __shared__ float s_m[27 * 16];     // [stat][warp]
    const int b = blockIdx.y;
    const float* xb = x + (size_t)b * NN * 3;
    const int tid = threadIdx.x, lane = tid & 31, w = tid >> 5;

    for (int t = tid; t < NN; t += 512) {
        float px = xb[t * 3 + 0], py = xb[t * 3 + 1], pz = xb[t * 3 + 2];
        pts[t] = make_float4(px, py, pz, px * px + py * py + pz * pz);
    }
    __syncthreads();

    const int i = blockIdx.x * QPB + w;
    float4 q = pts[i];
    const float qx = 2.f * q.x, qy = 2.f * q.y, qz = 2.f * q.z;

    unsigned my_k = (lane < KK) ? okey(-FLT_MAX) : okey(FLT_MAX);
    int      my_j = 0x7fff0000 | lane;
    unsigned wkey = okey(-FLT_MAX);

    for (int jc = 0; jc < NN; jc += 32) {
        float4 p = pts[jc + lane];
        float s = fmaf(qx, p.x, fmaf(qy, p.y, fmaf(qz, p.z, -p.w)));
        unsigned k = okey(s);
        unsigned mask = __ballot_sync(0xffffffffu, k > wkey);
        while (mask) {
            const int l = __ffs(mask) - 1;
            mask &= mask - 1;
            const unsigned kc = __shfl_sync(0xffffffffu, k, l);
            if (kc > wkey) {
                const unsigned umin = __reduce_min_sync(0xffffffffu, my_k);
                const bool tied = (my_k == umin);
                const int jmax = __reduce_max_sync(0xffffffffu, tied ? my_j : -1);
                if (tied && my_j == jmax) { my_k = kc; my_j = jc + l; }
                wkey = __reduce_min_sync(0xffffffffu, my_k);
            }
        }
    }

    if (lane < KK)
        idxo[((size_t)b * NN + i) * KK + lane] = my_j;

    // ---- fused BN1 f-moment stats (per-query; pts still resident) ----
    const bool ok = (lane < KK);
    float4 pj = pts[ok ? my_j : 0];
    float f[6];
    f[0] = ok ? (pj.x - q.x) : 0.f;
    f[1] = ok ? (pj.y - q.y) : 0.f;
    f[2] = ok ? (pj.z - q.z) : 0.f;
    f[3] = ok ? q.x : 0.f;
    f[4] = ok ? q.y : 0.f;
    f[5] = ok ? q.z : 0.f;

    float acc[27];
#pragma unroll
    for (int d = 0; d < 6; d++) acc[d] = f[d];
    {
        int k = 6;
#pragma unroll
        for (int d = 0; d < 6; d++)
#pragma unroll
            for (int e = d; e < 6; e++) acc[k++] = f[d] * f[e];
    }
#pragma unroll
    for (int s = 0; s < 27; s++) {
        float v = acc[s];
#pragma unroll
        for (int m = 16; m > 0; m >>= 1)
            v += __shfl_xor_sync(0xffffffffu, v, m);
        if (lane == 0) s_m[s * 16 + w] = v;
    }
    __syncthreads();

    if (tid < 27) {
        float a = 0.f;
#pragma unroll
        for (int ww = 0; ww < 16; ww++) a += s_m[tid * 16 + ww];
        pf[tid * NBK + blockIdx.y * (NN / QPB) + blockIdx.x] = a;
    }
}

// ---------------------------------------------------------------------------
// affine1: warp-parallel moment reduction -> analytic BN1 affine (proven).
// ---------------------------------------------------------------------------
__global__ void affine1_kernel(const float* __restrict__ pf, int nb,
                               const float* __restrict__ W1,
                               const float* __restrict__ b1,
                               const float* __restrict__ g1,
                               const float* __restrict__ be1,
                               float* __restrict__ sc,
                               float* __restrict__ sh)
{
    __shared__ double st[32];
    const int lane = threadIdx.x & 31;
    const int warp = threadIdx.x >> 5;

#pragma unroll
    for (int g = 0; g < 4; ++g) {
        const int s = warp + g * 8;
        if (s < 27) {
            double a = 0.0;
            for (int i = lane; i < nb; i += 32)
                a += (double)pf[s * nb + i];
#pragma unroll
            for (int m = 16; m > 0; m >>= 1)
                a += __shfl_xor_sync(0xffffffffu, a, m);
            if (lane == 0) st[s] = a;
        }
    }
    __syncthreads();

    if (threadIdx.x < 64) {
        const int c = threadIdx.x;
        double w[6];
#pragma unroll
        for (int d = 0; d < 6; d++) w[d] = (double)W1[c * 6 + d];
        const double b = (double)b1[c];
        double ws = 0.0;
#pragma unroll
        for (int d = 0; d < 6; d++) ws += w[d] * st[d];
        double wmw = 0.0;
        int k = 6;
#pragma unroll
        for (int d = 0; d < 6; d++)
#pragma unroll
            for (int e = d; e < 6; e++, k++)
                wmw += ((d == e) ? w[d] * w[d] : 2.0 * w[d] * w[e]) * st[k];
        const double Pd = (double)PP;
        double mean = ws / Pd + b;
        double e2   = (wmw + 2.0 * b * ws) / Pd + b * b;
        double var  = e2 - mean * mean;
        double inv  = (double)g1[c] / sqrt(var + 1e-5);
        sc[c] = (float)inv;
        sh[c] = (float)((double)be1[c] - mean * inv);
    }
}

// ---------------------------------------------------------------------------
// Reduce per-block partials -> fused BN affine (proven).
// ---------------------------------------------------------------------------
__global__ void reduce_kernel(const float* __restrict__ ps,
                              const float* __restrict__ pq, int nb,
                              const float* __restrict__ gamma,
                              const float* __restrict__ beta,
                              float* __restrict__ scale,
                              float* __restrict__ shift)
{
    const int c = blockIdx.x;
    double s = 0.0, q = 0.0;
    for (int i = threadIdx.x; i < nb; i += 256) {
        s += (double)ps[c * nb + i];
        q += (double)pq[c * nb + i];
    }
    __shared__ double r1[256], r2[256];
    r1[threadIdx.x] = s; r2[threadIdx.x] = q;
    __syncthreads();
    for (int off = 128; off > 0; off >>= 1) {
        if (threadIdx.x < off) {
            r1[threadIdx.x] += r1[threadIdx.x + off];
            r2[threadIdx.x] += r2[threadIdx.x + off];
        }
        __syncthreads();
    }
    if (threadIdx.x == 0) {
        double mean = r1[0] / (double)PP;
        double var  = r2[0] / (double)PP - mean * mean;
        double inv  = (double)gamma[c] / sqrt(var + 1e-5);
        scale[c] = (float)inv;
        shift[c] = (float)((double)beta[c] - mean * inv);
    }
}

// ---------------------------------------------------------------------------
// Fused conv1+BN1+relu+conv2 GEMM (measured 153.6us — unchanged).
// ---------------------------------------------------------------------------
__global__ void __launch_bounds__(256, 2) gemm_fused_kernel(
    const float* __restrict__ x,
    const int* __restrict__ idx,
    const float* __restrict__ W1,
    const float* __restrict__ b1,
    const float* __restrict__ sc1,
    const float* __restrict__ sh1,
    const float* __restrict__ W,     // W2 [128][64]
    const float* __restrict__ bias,  // b2
    float* __restrict__ yout,
    float* __restrict__ ps,
    float* __restrict__ pq)
{
    extern __shared__ float sh[];
    float* Wsh   = sh;                     // [64][132] transposed W2
    float* Ash   = Wsh + 64 * 132;         // [64][128]
    float* fs    = Ash + 64 * 128;         // [128][7]
    float* W1sh  = fs + 128 * 7;           // [64][6]
    float* b1sh  = W1sh + 64 * 6;          // [64]
    float* sc1sh = b1sh + 64;              // [64]
    float* sh1sh = sc1sh + 64;             // [64]
    const int tid = threadIdx.x;

    for (int t = tid; t < 128 * 64; t += 256) {
        int o = t >> 6, c = t & 63;
        Wsh[c * 132 + o] = W[t];
    }
    for (int t = tid; t < 64 * 6; t += 256) W1sh[t] = W1[t];
    if (tid < 64) {
        b1sh[tid]  = b1[tid];
        sc1sh[tid] = sc1[tid];
        sh1sh[tid] = sh1[tid];
    }

    const int pbase = blockIdx.x * 128;
    if (tid < 128) {
        const int p  = pbase + tid;
        const int bn = p / KK;
        const int b  = bn >> 12;
        const int j  = idx[p];
        const float* xi = x + (size_t)bn * 3;
        const float* xj = x + ((size_t)b * NN + j) * 3;
        float xi0 = xi[0], xi1 = xi[1], xi2 = xi[2];
        fs[tid * 7 + 0] = xj[0] - xi0;
        fs[tid * 7 + 1] = xj[1] - xi1;
        fs[tid * 7 + 2] = xj[2] - xi2;
        fs[tid * 7 + 3] = xi0;
        fs[tid * 7 + 4] = xi1;
        fs[tid * 7 + 5] = xi2;
    }
    __syncthreads();

    for (int t = tid; t < 64 * 128; t += 256) {
        int c = t >> 7, p = t & 127;
        const float* w = W1sh + c * 6;
        const float* f = fs + p * 7;
        float a = b1sh[c];
        a = fmaf(w[0], f[0], a);
        a = fmaf(w[1], f[1], a);
        a = fmaf(w[2], f[2], a);
        a = fmaf(w[3], f[3], a);
        a = fmaf(w[4], f[4], a);
        a = fmaf(w[5], f[5], a);
        Ash[t] = fmaxf(fmaf(a, sc1sh[c], sh1sh[c]), 0.f);
    }
    __syncthreads();

    const int tx = tid & 15;
    const int ty = tid >> 4;

    unsigned long long acc[8][4];
#pragma unroll
    for (int i = 0; i < 8; i++)
#pragma unroll
        for (int jp = 0; jp < 4; jp++) acc[i][jp] = 0ULL;

#pragma unroll 4
    for (int c = 0; c < 64; ++c) {
        ulonglong2 A0 = *(const ulonglong2*)(Ash + c * 128 + tx * 4);
        ulonglong2 A1 = *(const ulonglong2*)(Ash + c * 128 + 64 + tx * 4);
        unsigned long long av[4] = {A0.x, A0.y, A1.x, A1.y};
        float4 w0 = *(const float4*)(Wsh + c * 132 + ty * 4);
        float4 w1 = *(const float4*)(Wsh + c * 132 + 64 + ty * 4);
        float wf[8] = {w0.x, w0.y, w0.z, w0.w, w1.x, w1.y, w1.z, w1.w};
#pragma unroll
        for (int i = 0; i < 8; i++) {
            unsigned long long wsp = splat2(wf[i]);
#pragma unroll
            for (int jp = 0; jp < 4; jp++) ffma2(acc[i][jp], wsp, av[jp]);
        }
    }

#pragma unroll
    for (int i = 0; i < 8; i++) {
        const int o = (i < 4) ? (ty * 4 + i) : (64 + ty * 4 + (i - 4));
        const float bo = bias[o];
        float2 p0 = unpack2(acc[i][0]);
        float2 p1 = unpack2(acc[i][1]);
        float2 p2 = unpack2(acc[i][2]);
        float2 p3 = unpack2(acc[i][3]);
        float v0 = p0.x + bo, v1 = p0.y + bo, v2 = p1.x + bo, v3 = p1.y + bo;
        float v4 = p2.x + bo, v5 = p2.y + bo, v6 = p3.x + bo, v7 = p3.y + bo;
        float* dst = yout + (size_t)o * PP + pbase;
        *(float4*)(dst + tx * 4)      = make_float4(v0, v1, v2, v3);
        *(float4*)(dst + 64 + tx * 4) = make_float4(v4, v5, v6, v7);

        float s = v0 + v1 + v2 + v3 + v4 + v5 + v6 + v7;
        float q = v0 * v0 + v1 * v1 + v2 * v2 + v3 * v3
                + v4 * v4 + v5 * v5 + v6 * v6 + v7 * v7;
#pragma unroll
        for (int m = 8; m > 0; m >>= 1) {
            s += __shfl_xor_sync(0xffffffffu, s, m, 16);
            q += __shfl_xor_sync(0xffffffffu, q, m, 16);
        }
        if (tx == 0) {
            ps[(size_t)o * NBG + blockIdx.x] = s;
            pq[(size_t)o * NBG + blockIdx.x] = q;
        }
    }
}

// ---------------------------------------------------------------------------
// GEMM (R14-proven): FFMA2 inner loop, 64-deep k-chunks, 2 blocks/SM. CIN=128.
// ---------------------------------------------------------------------------
template <int CIN>
__global__ void __launch_bounds__(256, 2) gemm_kernel(
    const float* __restrict__ yin,
    const float* __restrict__ W,
    const float* __restrict__ bias,
    const float* __restrict__ scale,
    const float* __restrict__ shift,
    float* __restrict__ yout,
    float* __restrict__ ps,
    float* __restrict__ pq)
{
    extern __shared__ float sh[];
    float* Wsh = sh;                  // transposed [CIN][132]
    float* Ash = sh + 132 * CIN;      // [64][128] k-chunk
    const int tid = threadIdx.x;

    for (int t = tid; t < 128 * CIN; t += 256) {
        int o = t / CIN, c = t - o * CIN;
        Wsh[c * 132 + o] = W[t];
    }

    const int pbase = blockIdx.x * 128;
    const int tx = tid & 15;
    const int ty = tid >> 4;

    unsigned long long acc[8][4];
#pragma unroll
    for (int i = 0; i < 8; i++)
#pragma unroll
        for (int jp = 0; jp < 4; jp++) acc[i][jp] = 0ULL;

#pragma unroll
    for (int kc = 0; kc < CIN / 64; ++kc) {
        __syncthreads();
        for (int t = tid; t < 64 * 128; t += 256) {
            int c = t >> 7, p = t & 127;
            int cg = kc * 64 + c;
            float v = yin[(size_t)cg * PP + pbase + p];
            v = fmaf(v, scale[cg], shift[cg]);
            Ash[t] = fmaxf(v, 0.f);
        }
        __syncthreads();

#pragma unroll 4
        for (int c = 0; c < 64; ++c) {
            const int cg = kc * 64 + c;
            ulonglong2 A0 = *(const ulonglong2*)(Ash + c * 128 + tx * 4);
            ulonglong2 A1 = *(const ulonglong2*)(Ash + c * 128 + 64 + tx * 4);
            unsigned long long av[4] = {A0.x, A0.y, A1.x, A1.y};
            float4 w0 = *(const float4*)(Wsh + cg * 132 + ty * 4);
            float4 w1 = *(const float4*)(Wsh + cg * 132 + 64 + ty * 4);
            float wf[8] = {w0.x, w0.y, w0.z, w0.w, w1.x, w1.y, w1.z, w1.w};
#pragma unroll
            for (int i = 0; i < 8; i++) {
                unsigned long long wsp = splat2(wf[i]);
#pragma unroll
                for (int jp = 0; jp < 4; jp++) ffma2(acc[i][jp], wsp, av[jp]);
            }
        }
    }

#pragma unroll
    for (int i = 0; i < 8; i++) {
        const int o = (i < 4) ? (ty * 4 + i) : (64 + ty * 4 + (i - 4));
        const float bo = bias[o];
        float2 p0 = unpack2(acc[i][0]);
        float2 p1 = unpack2(acc[i][1]);
        float2 p2 = unpack2(acc[i][2]);
        float2 p3 = unpack2(acc[i][3]);
        float v0 = p0.x + bo, v1 = p0.y + bo, v2 = p1.x + bo, v3 = p1.y + bo;
        float v4 = p2.x + bo, v5 = p2.y + bo, v6 = p3.x + bo, v7 = p3.y + bo;
        float* dst = yout + (size_t)o * PP + pbase;
        *(float4*)(dst + tx * 4)      = make_float4(v0, v1, v2, v3);
        *(float4*)(dst + 64 + tx * 4) = make_float4(v4, v5, v6, v7);

        float s = v0 + v1 + v2 + v3 + v4 + v5 + v6 + v7;
        float q = v0 * v0 + v1 * v1 + v2 * v2 + v3 * v3
                + v4 * v4 + v5 * v5 + v6 * v6 + v7 * v7;
#pragma unroll
        for (int m = 8; m > 0; m >>= 1) {
            s += __shfl_xor_sync(0xffffffffu, s, m, 16);
            q += __shfl_xor_sync(0xffffffffu, q, m, 16);
        }
        if (tx == 0) {
            ps[(size_t)o * NBG + blockIdx.x] = s;
            pq[(size_t)o * NBG + blockIdx.x] = q;
        }
    }
}

// ---------------------------------------------------------------------------
// Max over k with final BN affine applied elementwise (proven).
// ---------------------------------------------------------------------------
__global__ void maxk_kernel(const float* __restrict__ y3,
                            const float* __restrict__ scale,
                            const float* __restrict__ shift,
                            float* __restrict__ out)
{
    const int n = blockIdx.x * blockDim.x + threadIdx.x;
    const int o = blockIdx.y;
    const int b = blockIdx.z;
    const float sc = scale[o], sf = shift[o];
    const float4* base =
        (const float4*)(y3 + (size_t)o * PP + ((size_t)b * NN + n) * KK);
    float m = -FLT_MAX;
#pragma unroll
    for (int q = 0; q < 5; ++q) {
        float4 v = base[q];
        m = fmaxf(m, fmaf(v.x, sc, sf));
        m = fmaxf(m, fmaf(v.y, sc, sf));
        m = fmaxf(m, fmaf(v.z, sc, sf));
        m = fmaxf(m, fmaf(v.w, sc, sf));
    }
    out[((size_t)b * 128 + o) * NN + n] = m;
}

// ---------------------------------------------------------------------------
// Launcher: graph-capturable, allocation-free.
// ---------------------------------------------------------------------------
extern "C" void kernel_launch(void* const* d_in, const int* in_sizes, int n_in,
                              void* d_out, int out_size)
{
    const float* x   = (const float*)d_in[0];
    const float* W1  = (const float*)d_in[1];
    const float* b1  = (const float*)d_in[2];
    const float* g1  = (const float*)d_in[3];
    const float* be1 = (const float*)d_in[4];
    const float* W2  = (const float*)d_in[5];
    const float* b2  = (const float*)d_in[6];
    const float* g2  = (const float*)d_in[7];
    const float* be2 = (const float*)d_in[8];
    const float* W3  = (const float*)d_in[9];
    const float* b3  = (const float*)d_in[10];
    const float* g3  = (const float*)d_in[11];
    const float* be3 = (const float*)d_in[12];
    float* out = (float*)d_out;

    void *y2p, *y3p, *idxp, *pfp, *psp, *pqp;
    void *sc1p, *sh1p, *sc2p, *sh2p, *sc3p, *sh3p;
    cudaGetSymbolAddress(&y2p,  g_y2);
    cudaGetSymbolAddress(&y3p,  g_y3);
    cudaGetSymbolAddress(&idxp, g_idx);
    cudaGetSymbolAddress(&pfp,  g_pf);
    cudaGetSymbolAddress(&psp,  g_ps);
    cudaGetSymbolAddress(&pqp,  g_pq);
    cudaGetSymbolAddress(&sc1p, g_sc1);  cudaGetSymbolAddress(&sh1p, g_sh1);
    cudaGetSymbolAddress(&sc2p, g_sc2);  cudaGetSymbolAddress(&sh2p, g_sh2);
    cudaGetSymbolAddress(&sc3p, g_sc3);  cudaGetSymbolAddress(&sh3p, g_sh3);

    const int smemF   = (64 * 132 + 64 * 128 + 128 * 7 + 64 * 6 + 3 * 64) * 4; // 72448
    const int smem128 = (132 * 128 + 64 * 128) * 4;                             // 100352
    cudaFuncSetAttribute(knn_warp_kernel,  cudaFuncAttributeMaxDynamicSharedMemorySize, 65536);
    cudaFuncSetAttribute(gemm_fused_kernel,cudaFuncAttributeMaxDynamicSharedMemorySize, smemF);
    cudaFuncSetAttribute(gemm_kernel<128>, cudaFuncAttributeMaxDynamicSharedMemorySize, smem128);

    // K0: kNN + fused BN1 f-moment partials
    knn_warp_kernel<<<dim3(NN / QPB, BB), 512, 65536>>>(x, (int*)idxp, (float*)pfp);

    // BN1 analytic affine from f-moments
    affine1_kernel<<<1, 256>>>((const float*)pfp, NBK, W1, b1, g1, be1,
                               (float*)sc1p, (float*)sh1p);

    // conv1+BN1+relu+conv2 fused + BN2 partials
    gemm_fused_kernel<<<NBG, 256, smemF>>>(x, (const int*)idxp, W1, b1,
                                           (const float*)sc1p, (const float*)sh1p,
                                           W2, b2, (float*)y2p,
                                           (float*)psp, (float*)pqp);
    reduce_kernel<<<128, 256>>>((const float*)psp, (const float*)pqp, NBG,
                                g2, be2, (float*)sc2p, (float*)sh2p);

    // conv3 on relu(BN2(y2)) + BN3 partials
    gemm_kernel<128><<<NBG, 256, smem128>>>((const float*)y2p, W3, b3,
                                            (const float*)sc2p, (const float*)sh2p,
                                            (float*)y3p, (float*)psp, (float*)pqp);
    reduce_kernel<<<128, 256>>>((const float*)psp, (const float*)pqp, NBG,
                                g3, be3, (float*)sc3p, (float*)sh3p);

    // BN3 affine + max over k
    maxk_kernel<<<dim3(NN / 256, 128, BB), 256>>>((const float*)y3p,
                                                  (const float*)sc3p, (const float*)sh3p,
                                                  out);
}